// round 15
// baseline (speedup 1.0000x reference)
#include <cuda_runtime.h>
#include <cstdint>

#define NHID   512
#define NCLS   250
#define WROWS  200
#define OUTW   450
#define MAXTOK 2048
#define WCTA   (2 * NCLS)     // 500 words CTAs (2 per class, ROW-split)

// ---- packed fp32x2 FMA (FFMA2): PTX-only on sm_103a, 2x FFMA throughput ----
__device__ __forceinline__ void fma2(unsigned long long& acc,
                                     unsigned long long a,
                                     unsigned long long b) {
    asm("fma.rn.f32x2 %0, %1, %2, %0;" : "+l"(acc) : "l"(a), "l"(b));
}
__device__ __forceinline__ float2 u2f(unsigned long long v) {
    float2 f;
    asm("mov.b64 {%0, %1}, %2;" : "=f"(f.x), "=f"(f.y) : "l"(v));
    return f;
}

// ---- sweep rows [r0, r1) of W for this warp's 8 register-resident tokens.
// Lane = (ks = lane>>2 of 8 k-slices, tq = lane&3). k-interleave: lane ks owns
// 16B units u with u%8==ks, so each j-step is one warp-coalesced 128B line of
// W streamed straight from GMEM (read-once, no smem, no barriers).
__device__ __forceinline__ void rows_sweep(
    const ulonglong2* __restrict__ W,      // row stride = 128 ulonglong2 (2KB)
    const float* __restrict__ bias,
    int r0, int r1, int colbase,
    const ulonglong2* xA, const ulonglong2* xB,   // [16] each, registers
    int tokA, int tokB, bool vA, bool vB,
    float* __restrict__ out, int lane, int ks) {
    for (int r = r0; r < r1; r++) {
        const ulonglong2* wr = W + (size_t)r * 128 + ks;
        unsigned long long a0 = 0, a1 = 0, b0 = 0, b1 = 0;
#pragma unroll
        for (int j = 0; j < 16; j++) {
            ulonglong2 w = wr[j * 8];      // LDG.128, 16 batched per row
            fma2(a0, w.x, xA[j].x);
            fma2(a1, w.y, xA[j].y);
            fma2(b0, w.x, xB[j].x);
            fma2(b1, w.y, xB[j].y);
        }
        float2 fa0 = u2f(a0), fa1 = u2f(a1);
        float2 fb0 = u2f(b0), fb1 = u2f(b1);
        float sA = (fa0.x + fa0.y) + (fa1.x + fa1.y);
        float sB = (fb0.x + fb0.y) + (fb1.x + fb1.y);
        sA += __shfl_xor_sync(0xffffffffu, sA, 4);
        sB += __shfl_xor_sync(0xffffffffu, sB, 4);
        sA += __shfl_xor_sync(0xffffffffu, sA, 8);
        sB += __shfl_xor_sync(0xffffffffu, sB, 8);
        sA += __shfl_xor_sync(0xffffffffu, sA, 16);
        sB += __shfl_xor_sync(0xffffffffu, sB, 16);
        if (lane < 4) {                    // lanes 0-3 hold tq 0-3
            const float bi = __ldg(bias + r);
            if (vA) out[(size_t)tokA * OUTW + colbase + r] = sA + bi;
            if (vB) out[(size_t)tokB * OUTW + colbase + r] = sB + bi;
        }
    }
}

__global__ __launch_bounds__(128, 4)
void decoder_kernel(const float* __restrict__ x,
                    const float* __restrict__ Wc,
                    const float* __restrict__ bc,
                    const float* __restrict__ Ww,
                    const float* __restrict__ bw,
                    const int* __restrict__ cls_raw,
                    float* __restrict__ out, int n) {
    __shared__ int s_tok[MAXTOK];
    __shared__ int s_cnt, s_not64;
    const int tid = threadIdx.x;
    const int warp = tid >> 5, lane = tid & 31;
    const int ks = lane >> 2, tq = lane & 3;
    const int bi = blockIdx.x;
    const ulonglong2* xg = (const ulonglong2*)x;

    if (bi < WCTA) {
        // ---- words: 2 CTAs per class, ROW-split (each CTA: all tokens) ----
        // Row split (not token split) makes the nondeterministic order of the
        // atomicAdd compaction harmless: each (token,row) has ONE writer.
        const int c = bi >> 1, pairidx = bi & 1;
        if (tid == 0) { s_cnt = 0; s_not64 = 0; }
        __syncthreads();
        // int32 vs int64 detection: odd int32 slots of int64 values in
        // [0,250) are all zero; int32 class values are not all zero.
        int flag = 0;
        for (int j = 2 * tid + 1; j < n; j += 256)
            if (cls_raw[j] != 0) flag = 1;
        if (flag) s_not64 = 1;
        __syncthreads();
        const int is64 = !s_not64;
        for (int i = tid; i < n; i += 128) {
            int cc = is64 ? cls_raw[2 * i] : cls_raw[i];
            if (cc == c) {
                int p = atomicAdd(&s_cnt, 1);
                if (p < MAXTOK) s_tok[p] = i;
            }
        }
        __syncthreads();
        const int cnt = min(s_cnt, MAXTOK);
        if (cnt == 0) return;

        const ulonglong2* Wg =
            (const ulonglong2*)Ww + (size_t)c * WROWS * 128;
        const float* biasw = bw + (size_t)c * WROWS;
        // rows: CTA pairidx owns 100 rows; each warp owns 25
        const int r0 = pairidx * 100 + warp * 25, r1 = r0 + 25;

        for (int base = 0; base < cnt; base += 8) {
            const int tpA = base + tq, tpB = base + 4 + tq;
            const bool vA = tpA < cnt, vB = tpB < cnt;
            const int tokA = s_tok[vA ? tpA : cnt - 1];
            const int tokB = s_tok[vB ? tpB : cnt - 1];
            ulonglong2 xA[16], xB[16];
            const ulonglong2* pA = xg + (size_t)tokA * 128 + ks;
            const ulonglong2* pB = xg + (size_t)tokB * 128 + ks;
#pragma unroll
            for (int j = 0; j < 16; j++) { xA[j] = pA[j * 8]; xB[j] = pB[j * 8]; }
            rows_sweep(Wg, biasw, r0, r1, NCLS, xA, xB,
                       tokA, tokB, vA, vB, out, lane, ks);
        }
    } else {
        // ------- cls: 32 tokens x half of Wc per CTA (Wc is L2-hot) -------
        const int q = bi - WCTA;
        const int tg = q >> 1, half = q & 1;
        const int t0 = tg * 32;
        if (t0 >= n) return;
        const int rbase = half * 125, rend = rbase + 125;

        const int tpA = t0 + warp * 8 + tq, tpB = tpA + 4;
        const bool vA = tpA < n, vB = tpB < n;
        const int tokA = vA ? tpA : n - 1;
        const int tokB = vB ? tpB : n - 1;
        ulonglong2 xA[16], xB[16];
        const ulonglong2* pA = xg + (size_t)tokA * 128 + ks;
        const ulonglong2* pB = xg + (size_t)tokB * 128 + ks;
#pragma unroll
        for (int j = 0; j < 16; j++) { xA[j] = pA[j * 8]; xB[j] = pB[j * 8]; }
        rows_sweep((const ulonglong2*)Wc, bc, rbase, rend, 0, xA, xB,
                   tokA, tokB, vA, vB, out, lane, ks);
    }
}

extern "C" void kernel_launch(void* const* d_in, const int* in_sizes, int n_in,
                              void* d_out, int out_size) {
    const float* x  = (const float*)d_in[0];
    const float* Wc = (const float*)d_in[1];
    const float* bc = (const float*)d_in[2];
    const float* Ww = (const float*)d_in[3];
    const float* bw = (const float*)d_in[4];
    const int*   ci = (const int*)d_in[5];
    const int n = in_sizes[0] / NHID;
    float* out = (float*)d_out;

    const int grid = WCTA + 2 * ((n + 31) / 32);
    decoder_kernel<<<grid, 128>>>(x, Wc, bc, Ww, bw, ci, out, n);
}

// round 16
// speedup vs baseline: 2.4438x; 2.4438x over previous
#include <cuda_runtime.h>
#include <cstdint>

#define NHID   512
#define NCLS   250
#define WROWS  200
#define OUTW   450
#define MAXTOK 2048
#define WCTA   (2 * NCLS)     // 500 words CTAs (2 per class, ROW-split)

// ---- packed fp32x2 FMA (FFMA2): PTX-only on sm_103a, 2x FFMA throughput ----
__device__ __forceinline__ void fma2(unsigned long long& acc,
                                     unsigned long long a,
                                     unsigned long long b) {
    asm("fma.rn.f32x2 %0, %1, %2, %0;" : "+l"(acc) : "l"(a), "l"(b));
}
__device__ __forceinline__ float2 u2f(unsigned long long v) {
    float2 f;
    asm("mov.b64 {%0, %1}, %2;" : "=f"(f.x), "=f"(f.y) : "l"(v));
    return f;
}

// ---- sweep rows [r0, r1) of W for this warp's 4 register-resident tokens.
// Lane = (ks = lane>>2 of 8 k-slices, tq = lane&3): ONE token per lane,
// 64 floats = 64 regs (fits 128-reg budget, no spill). k-interleave: lane ks
// owns 16B units u with u%8==ks, so each j-step is one warp-coalesced 128B
// line of W streamed straight from GMEM (no smem, no barriers).
__device__ __forceinline__ void rows_sweep(
    const ulonglong2* __restrict__ W,      // row stride = 128 ulonglong2 (2KB)
    const float* __restrict__ bias,
    int r0, int r1, int colbase,
    const ulonglong2* xr,                  // [16] registers (64 floats)
    int tok, bool valid,
    float* __restrict__ out, int lane) {
    const int ks = lane >> 2;
#pragma unroll 2
    for (int r = r0; r < r1; r++) {
        const ulonglong2* wr = W + (size_t)r * 128 + ks;
        unsigned long long a0 = 0, a1 = 0;
#pragma unroll
        for (int j = 0; j < 16; j++) {
            ulonglong2 w = wr[j * 8];      // LDG.128, 16 independent per row
            fma2(a0, w.x, xr[j].x);
            fma2(a1, w.y, xr[j].y);
        }
        float2 f0 = u2f(a0), f1 = u2f(a1);
        float s = (f0.x + f0.y) + (f1.x + f1.y);
        s += __shfl_xor_sync(0xffffffffu, s, 4);    // fold 8 k-slices
        s += __shfl_xor_sync(0xffffffffu, s, 8);
        s += __shfl_xor_sync(0xffffffffu, s, 16);
        if (lane < 4 && valid)             // lanes 0-3 hold tq 0-3
            out[(size_t)tok * OUTW + colbase + r] = s + __ldg(bias + r);
    }
}

__global__ __launch_bounds__(128, 4)
void decoder_kernel(const float* __restrict__ x,
                    const float* __restrict__ Wc,
                    const float* __restrict__ bc,
                    const float* __restrict__ Ww,
                    const float* __restrict__ bw,
                    const int* __restrict__ cls_raw,
                    float* __restrict__ out, int n) {
    __shared__ int s_tok[MAXTOK];
    __shared__ int s_cnt, s_not64;
    const int tid = threadIdx.x;
    const int warp = tid >> 5, lane = tid & 31;
    const int ks = lane >> 2, tq = lane & 3;
    const int bi = blockIdx.x;
    const ulonglong2* xg = (const ulonglong2*)x;

    if (bi < WCTA) {
        // ---- words: 2 CTAs per class, ROW-split (each CTA: all tokens) ----
        // Row split keeps the nondeterministic atomicAdd compaction order
        // harmless: each (token,row) output has exactly one writer.
        const int c = bi >> 1, pairidx = bi & 1;
        if (tid == 0) { s_cnt = 0; s_not64 = 0; }
        __syncthreads();
        // int32 vs int64 detection: odd int32 slots of int64 values in
        // [0,250) are all zero; int32 class values are not all zero.
        int flag = 0;
        for (int j = 2 * tid + 1; j < n; j += 256)
            if (cls_raw[j] != 0) flag = 1;
        if (flag) s_not64 = 1;
        __syncthreads();
        const int is64 = !s_not64;
        for (int i = tid; i < n; i += 128) {
            int cc = is64 ? cls_raw[2 * i] : cls_raw[i];
            if (cc == c) {
                int p = atomicAdd(&s_cnt, 1);
                if (p < MAXTOK) s_tok[p] = i;
            }
        }
        __syncthreads();
        const int cnt = min(s_cnt, MAXTOK);
        if (cnt == 0) return;

        const ulonglong2* Wg =
            (const ulonglong2*)Ww + (size_t)c * WROWS * 128;
        const float* biasw = bw + (size_t)c * WROWS;
        // rows: CTA pairidx owns 100; each warp owns 25
        const int r0 = pairidx * 100 + warp * 25, r1 = r0 + 25;

        for (int base = 0; base < cnt; base += 4) {
            const int tp = base + tq;
            const bool valid = tp < cnt;
            const int tok = s_tok[valid ? tp : cnt - 1];
            ulonglong2 xr[16];
            const ulonglong2* p = xg + (size_t)tok * 128 + ks;
#pragma unroll
            for (int j = 0; j < 16; j++) xr[j] = p[j * 8];
            rows_sweep(Wg, biasw, r0, r1, NCLS, xr, tok, valid, out, lane);
        }
    } else {
        // ------- cls: 16 tokens x half of Wc per CTA (Wc is L2-hot) -------
        const int q = bi - WCTA;
        const int tg = q >> 1, half = q & 1;
        const int t0 = tg * 16;
        if (t0 >= n) return;
        const int rbase = half * 125, rend = rbase + 125;

        const int tp = t0 + warp * 4 + tq;
        const bool valid = tp < n;
        const int tok = valid ? tp : n - 1;
        ulonglong2 xr[16];
        const ulonglong2* p = xg + (size_t)tok * 128 + ks;
#pragma unroll
        for (int j = 0; j < 16; j++) xr[j] = p[j * 8];
        rows_sweep((const ulonglong2*)Wc, bc, rbase, rend, 0, xr, tok, valid,
                   out, lane);
    }
}

extern "C" void kernel_launch(void* const* d_in, const int* in_sizes, int n_in,
                              void* d_out, int out_size) {
    const float* x  = (const float*)d_in[0];
    const float* Wc = (const float*)d_in[1];
    const float* bc = (const float*)d_in[2];
    const float* Ww = (const float*)d_in[3];
    const float* bw = (const float*)d_in[4];
    const int*   ci = (const int*)d_in[5];
    const int n = in_sizes[0] / NHID;
    float* out = (float*)d_out;

    const int grid = WCTA + 2 * ((n + 15) / 16);
    decoder_kernel<<<grid, 128>>>(x, Wc, bc, Ww, bw, ci, out, n);
}